// round 1
// baseline (speedup 1.0000x reference)
#include <cuda_runtime.h>
#include <cuda_bf16.h>
#include <cstdint>

// Problem constants (fixed shapes from reference):
//   v: [4,128,128,256] fp32 -> M = 65536 rows of DIM=256
//   Wq/Wk/Wv/Wp: [256,256], bp: [256]
//   Attention is ROW-LOCAL: per row, view as [8 heads][32], attn = softmax_g(q_h . k_g / sqrt(32)),
//   x[h] = sum_g attn[h][g] * vv[g]. Then out = x @ Wp + bp.

#define M_TOTAL 65536
#define DIM     256
#define NHEAD   8
#define HD      32

// Scratch (allocation-free rule: __device__ globals)
__device__ float g_qkv[(size_t)M_TOTAL * 3 * DIM];  // [M][768]: q | k | v
__device__ float g_x  [(size_t)M_TOTAL * DIM];      // [M][256]

// ---------------------------------------------------------------------------
// fp32 SGEMM: C[M,N] = A[M,K] @ B[K,N] (+ bias), C row stride ldc.
// BM=128, BN=128, BK=16, 256 threads, 8x8 per-thread tile.
// ---------------------------------------------------------------------------
template<bool BIAS>
__global__ __launch_bounds__(256, 2)
void sgemm_kernel(const float* __restrict__ A, const float* __restrict__ B,
                  const float* __restrict__ bias, float* __restrict__ C,
                  int M, int N, int K, int ldc)
{
    constexpr int BM = 128, BN = 128, BK = 16;
    __shared__ float As[BK][BM];   // A stored k-major (transposed)
    __shared__ float Bs[BK][BN];

    const int bx = blockIdx.x;     // N tile
    const int by = blockIdx.y;     // M tile
    const int tid = threadIdx.x;
    const int tx = tid & 15;       // N direction (x8)
    const int ty = tid >> 4;       // M direction (x8)

    float acc[8][8];
    #pragma unroll
    for (int i = 0; i < 8; i++)
        #pragma unroll
        for (int j = 0; j < 8; j++) acc[i][j] = 0.0f;

    const float* Atile = A + (size_t)by * BM * K;
    const float* Btile = B + (size_t)bx * BN;

    for (int k0 = 0; k0 < K; k0 += BK) {
        // Load A tile: 128x16 = 512 float4, 2 per thread. id -> m = id/4, kk = (id%4)*4
        #pragma unroll
        for (int i = 0; i < 2; i++) {
            int id = tid * 2 + i;
            int m  = id >> 2;
            int kk = (id & 3) << 2;
            float4 a = *(const float4*)(Atile + (size_t)m * K + k0 + kk);
            As[kk + 0][m] = a.x;
            As[kk + 1][m] = a.y;
            As[kk + 2][m] = a.z;
            As[kk + 3][m] = a.w;
        }
        // Load B tile: 16x128 = 512 float4. id -> kk = id/32, n = (id%32)*4
        #pragma unroll
        for (int i = 0; i < 2; i++) {
            int id = tid * 2 + i;
            int kk = id >> 5;
            int n  = (id & 31) << 2;
            *(float4*)(&Bs[kk][n]) = *(const float4*)(Btile + (size_t)(k0 + kk) * N + n);
        }
        __syncthreads();

        #pragma unroll
        for (int kk = 0; kk < BK; kk++) {
            float ar[8], br[8];
            #pragma unroll
            for (int i = 0; i < 8; i++) ar[i] = As[kk][ty * 8 + i];
            #pragma unroll
            for (int j = 0; j < 8; j++) br[j] = Bs[kk][tx * 8 + j];
            #pragma unroll
            for (int i = 0; i < 8; i++)
                #pragma unroll
                for (int j = 0; j < 8; j++)
                    acc[i][j] = fmaf(ar[i], br[j], acc[i][j]);
        }
        __syncthreads();
    }

    // Write back
    #pragma unroll
    for (int i = 0; i < 8; i++) {
        int m = by * BM + ty * 8 + i;
        #pragma unroll
        for (int j = 0; j < 8; j += 4) {
            int n = bx * BN + tx * 8 + j;
            float4 r = make_float4(acc[i][j], acc[i][j + 1], acc[i][j + 2], acc[i][j + 3]);
            if (BIAS) {
                r.x += bias[n + 0];
                r.y += bias[n + 1];
                r.z += bias[n + 2];
                r.w += bias[n + 3];
            }
            *(float4*)(C + (size_t)m * ldc + n) = r;
        }
    }
}

// ---------------------------------------------------------------------------
// Row-local head-mixing attention.
// 16 rows per CTA, 128 threads: thread = (row r = tid/8, head h = tid%8).
// smem holds 16 rows x 768 floats (q|k|v) = 48 KB.
// ---------------------------------------------------------------------------
__global__ __launch_bounds__(128)
void attn_kernel(const float* __restrict__ qkv, float* __restrict__ x)
{
    __shared__ float s[16 * 768];
    const int row0 = blockIdx.x * 16;
    const int tid  = threadIdx.x;

    // Cooperative load: 16*768 = 12288 floats = 3072 float4, 24 per thread
    const float4* src = (const float4*)(qkv + (size_t)row0 * 768);
    float4* dst = (float4*)s;
    #pragma unroll
    for (int i = 0; i < 24; i++)
        dst[tid + 128 * i] = src[tid + 128 * i];
    __syncthreads();

    const int r = tid >> 3;
    const int h = tid & 7;
    const float* q  = s + r * 768 + h * HD;
    const float* k  = s + r * 768 + 256;
    const float* vv = s + r * 768 + 512;

    const float scale = 0.17677669529663687f;  // 1/sqrt(32)

    float p[8];
    #pragma unroll
    for (int g = 0; g < 8; g++) {
        float a = 0.0f;
        #pragma unroll
        for (int d = 0; d < 32; d++)
            a = fmaf(q[d], k[g * 32 + d], a);
        p[g] = a * scale;
    }

    float mx = p[0];
    #pragma unroll
    for (int g = 1; g < 8; g++) mx = fmaxf(mx, p[g]);
    float sum = 0.0f;
    #pragma unroll
    for (int g = 0; g < 8; g++) { p[g] = __expf(p[g] - mx); sum += p[g]; }
    const float inv = 1.0f / sum;
    #pragma unroll
    for (int g = 0; g < 8; g++) p[g] *= inv;

    float o[32];
    #pragma unroll
    for (int d = 0; d < 32; d++) {
        float a = 0.0f;
        #pragma unroll
        for (int g = 0; g < 8; g++)
            a = fmaf(p[g], vv[g * 32 + d], a);
        o[d] = a;
    }

    float* xp = x + (size_t)(row0 + r) * 256 + h * 32;
    #pragma unroll
    for (int d = 0; d < 32; d += 4)
        *(float4*)(xp + d) = make_float4(o[d], o[d + 1], o[d + 2], o[d + 3]);
}

// ---------------------------------------------------------------------------
// Launch
// ---------------------------------------------------------------------------
extern "C" void kernel_launch(void* const* d_in, const int* in_sizes, int n_in,
                              void* d_out, int out_size)
{
    const float* v  = (const float*)d_in[0];
    const float* Wq = (const float*)d_in[1];
    const float* Wk = (const float*)d_in[2];
    const float* Wv = (const float*)d_in[3];
    const float* Wp = (const float*)d_in[4];
    const float* bp = (const float*)d_in[5];
    float* out = (float*)d_out;

    float* qkv = nullptr;
    float* xb  = nullptr;
    cudaGetSymbolAddress((void**)&qkv, g_qkv);
    cudaGetSymbolAddress((void**)&xb,  g_x);

    dim3 gproj(DIM / 128, M_TOTAL / 128);   // (2, 512)

    // q | k | v projections into packed qkv[M][768]
    sgemm_kernel<false><<<gproj, 256>>>(v, Wq, nullptr, qkv + 0,       M_TOTAL, DIM, DIM, 3 * DIM);
    sgemm_kernel<false><<<gproj, 256>>>(v, Wk, nullptr, qkv + DIM,     M_TOTAL, DIM, DIM, 3 * DIM);
    sgemm_kernel<false><<<gproj, 256>>>(v, Wv, nullptr, qkv + 2 * DIM, M_TOTAL, DIM, DIM, 3 * DIM);

    // Row-local attention
    attn_kernel<<<M_TOTAL / 16, 128>>>(qkv, xb);

    // Output projection with bias
    sgemm_kernel<true><<<gproj, 256>>>(xb, Wp, bp, out, M_TOTAL, DIM, DIM, DIM);
}

// round 3
// speedup vs baseline: 2.4799x; 2.4799x over previous
#include <cuda_runtime.h>
#include <cuda_bf16.h>
#include <cstdint>

// out = RowLocalAttn(v@Wq, v@Wk, v@Wv) @ Wp + bp
// v: [65536, 256] fp32. GEMMs via warp-level mma.sync bf16 (3-pass hi/lo split,
// fp32 accum). No sm_103a-specific instructions (harness targets plain sm_103).

#define M_TOTAL 65536
#define DIM     256

// ---------------- scratch (__device__ globals; no allocs allowed) ----------
__device__ __align__(128) unsigned short g_vhi[(size_t)M_TOTAL * DIM];
__device__ __align__(128) unsigned short g_vlo[(size_t)M_TOTAL * DIM];
__device__ __align__(128) float          g_qkv[(size_t)M_TOTAL * 3 * DIM]; // [M][768] q|k|v
__device__ __align__(128) unsigned short g_xhi[(size_t)M_TOTAL * DIM];
__device__ __align__(128) unsigned short g_xlo[(size_t)M_TOTAL * DIM];
// transposed split weights: [4 weights][hi/lo][n=256][k=256]
__device__ __align__(128) unsigned short g_wt[4 * 2 * 256 * 256];

// ---------------- PTX helpers (all portable, sm_80-era ISA) -----------------
__device__ __forceinline__ uint32_t smem_u32(const void* p) {
    uint32_t a;
    asm("{ .reg .u64 t; cvta.to.shared.u64 t, %1; cvt.u32.u64 %0, t; }" : "=r"(a) : "l"(p));
    return a;
}
__device__ __forceinline__ void cp_async16(uint32_t s, const void* g) {
    asm volatile("cp.async.cg.shared.global [%0], [%1], 16;" :: "r"(s), "l"(g));
}
__device__ __forceinline__ void cp_commit() {
    asm volatile("cp.async.commit_group;");
}
template<int N>
__device__ __forceinline__ void cp_wait() {
    asm volatile("cp.async.wait_group %0;" :: "n"(N));
}
__device__ __forceinline__ void ldsm4(uint32_t* r, uint32_t a) {
    asm volatile("ldmatrix.sync.aligned.m8n8.x4.shared.b16 {%0,%1,%2,%3}, [%4];"
        : "=r"(r[0]), "=r"(r[1]), "=r"(r[2]), "=r"(r[3]) : "r"(a));
}
__device__ __forceinline__ void mma16816(float* d, const uint32_t* a, const uint32_t* b) {
    asm volatile("mma.sync.aligned.m16n8k16.row.col.f32.bf16.bf16.f32 "
        "{%0,%1,%2,%3}, {%4,%5,%6,%7}, {%8,%9}, {%0,%1,%2,%3};"
        : "+f"(d[0]), "+f"(d[1]), "+f"(d[2]), "+f"(d[3])
        : "r"(a[0]), "r"(a[1]), "r"(a[2]), "r"(a[3]), "r"(b[0]), "r"(b[1]));
}

// swizzled offset inside a 128-row x 64-byte tile (16B granules)
__device__ __forceinline__ uint32_t swz(int row, int c) {
    return (uint32_t)(row * 64 + ((c ^ ((row >> 1) & 3)) << 4));
}

// ---------------- conversion kernels ---------------------------------------
__global__ __launch_bounds__(256)
void split_kernel(const float4* __restrict__ in, uint2* __restrict__ hi,
                  uint2* __restrict__ lo, int n4)
{
    int i = blockIdx.x * blockDim.x + threadIdx.x;
    if (i >= n4) return;
    float4 f = in[i];
    __nv_bfloat16 h0 = __float2bfloat16(f.x);
    __nv_bfloat16 h1 = __float2bfloat16(f.y);
    __nv_bfloat16 h2 = __float2bfloat16(f.z);
    __nv_bfloat16 h3 = __float2bfloat16(f.w);
    __nv_bfloat16 l0 = __float2bfloat16(f.x - __bfloat162float(h0));
    __nv_bfloat16 l1 = __float2bfloat16(f.y - __bfloat162float(h1));
    __nv_bfloat16 l2 = __float2bfloat16(f.z - __bfloat162float(h2));
    __nv_bfloat16 l3 = __float2bfloat16(f.w - __bfloat162float(h3));
    __nv_bfloat162 hp0 = __nv_bfloat162(h0, h1), hp1 = __nv_bfloat162(h2, h3);
    __nv_bfloat162 lp0 = __nv_bfloat162(l0, l1), lp1 = __nv_bfloat162(l2, l3);
    uint2 ho, lo2;
    ho.x = *(uint32_t*)&hp0; ho.y = *(uint32_t*)&hp1;
    lo2.x = *(uint32_t*)&lp0; lo2.y = *(uint32_t*)&lp1;
    hi[i] = ho; lo[i] = lo2;
}

// transpose + split weights: wt[(wi*2+h)*65536 + n*256 + k] = split(W[k*256+n])
__global__ __launch_bounds__(256)
void wconv_kernel(const float* __restrict__ Wq, const float* __restrict__ Wk,
                  const float* __restrict__ Wv, const float* __restrict__ Wp,
                  unsigned short* __restrict__ wt)
{
    int wi = blockIdx.y;
    int n  = blockIdx.x;
    int k  = threadIdx.x;
    const float* W = (wi == 0) ? Wq : (wi == 1) ? Wk : (wi == 2) ? Wv : Wp;
    float val = W[k * 256 + n];
    __nv_bfloat16 h = __float2bfloat16(val);
    __nv_bfloat16 l = __float2bfloat16(val - __bfloat162float(h));
    wt[((size_t)(wi * 2 + 0) * 256 + n) * 256 + k] = *(unsigned short*)&h;
    wt[((size_t)(wi * 2 + 1) * 256 + n) * 256 + k] = *(unsigned short*)&l;
}

// ---------------- split-bf16 mma.sync GEMM ----------------------------------
// C[by*128..+128][bx*128..+128] = A @ B^T (+bias).  A split [M][256] bf16 hi/lo,
// B split [256 n][256 k] bf16 hi/lo.  3 passes accumulated in fp32.
// smem: 2 stages x { Ah 8K | Al 8K | Bh 8K | Bl 8K } = 64 KB (dynamic).
static constexpr int STAGE_BYTES = 32768;
static constexpr int OFF_AH = 0, OFF_AL = 8192, OFF_BH = 16384, OFF_BL = 24576;
static constexpr int GEMM_SMEM = 2 * STAGE_BYTES;

template<bool BIAS>
__global__ __launch_bounds__(256)
void gemm3_kernel(const unsigned short* __restrict__ Ahi, const unsigned short* __restrict__ Alo,
                  const unsigned short* __restrict__ Bhi, const unsigned short* __restrict__ Blo,
                  const float* __restrict__ bias, float* __restrict__ C, int ldc)
{
    extern __shared__ char smem[];
    const uint32_t sb = smem_u32(smem);
    const int tid  = threadIdx.x;
    const int wid  = tid >> 5;
    const int lane = tid & 31;
    const int mw = wid & 1;        // 2 warp rows (64 each)
    const int nw = wid >> 1;       // 4 warp cols (32 each)

    const int mbase = blockIdx.y * 128;
    const int nbase = blockIdx.x * 128;

    // ---- async-load one 32-wide K chunk into stage s ----
    auto load_chunk = [&](int kc, int s) {
        const uint32_t stg = sb + s * STAGE_BYTES;
        #pragma unroll
        for (int i = 0; i < 2; i++) {
            int u = tid + i * 256;             // 512 16B-units per 8K tile
            int row = u >> 2, c = u & 3;
            uint32_t so = swz(row, c);
            size_t ga = (size_t)(mbase + row) * 256 + kc * 32 + c * 8;
            size_t gb = (size_t)(nbase + row) * 256 + kc * 32 + c * 8;
            cp_async16(stg + OFF_AH + so, Ahi + ga);
            cp_async16(stg + OFF_AL + so, Alo + ga);
            cp_async16(stg + OFF_BH + so, Bhi + gb);
            cp_async16(stg + OFF_BL + so, Blo + gb);
        }
        cp_commit();
    };

    float acc[4][4][4];
    #pragma unroll
    for (int i = 0; i < 4; i++)
        #pragma unroll
        for (int j = 0; j < 4; j++)
            #pragma unroll
            for (int r = 0; r < 4; r++) acc[i][j][r] = 0.0f;

    load_chunk(0, 0);

    for (int kc = 0; kc < 8; kc++) {
        if (kc < 7) load_chunk(kc + 1, (kc + 1) & 1);
        if (kc < 7) cp_wait<1>(); else cp_wait<0>();
        __syncthreads();

        const uint32_t stg = sb + (kc & 1) * STAGE_BYTES;
        #pragma unroll
        for (int ks = 0; ks < 2; ks++) {
            // A fragments (4 m-tiles), hi+lo
            uint32_t a_hi[4][4], a_lo[4][4];
            {
                int arow = mw * 64 + (lane & 15);
                int ac   = ks * 2 + (lane >> 4);
                uint32_t base_off = swz(arow, ac);
                #pragma unroll
                for (int mt = 0; mt < 4; mt++) {
                    uint32_t off = base_off + mt * 16 * 64;
                    ldsm4(a_hi[mt], stg + OFF_AH + off);
                    ldsm4(a_lo[mt], stg + OFF_AL + off);
                }
            }
            // B fragments (4 n-tiles via 2 x ldsm4), hi+lo
            uint32_t b_hi[4][2], b_lo[4][2];
            {
                int nr0 = nw * 32 + ((lane >> 4) << 3) + (lane & 7);
                int bc  = ks * 2 + ((lane >> 3) & 1);
                #pragma unroll
                for (int nh = 0; nh < 2; nh++) {
                    uint32_t off = swz(nr0 + nh * 16, bc);
                    uint32_t r[4];
                    ldsm4(r, stg + OFF_BH + off);
                    b_hi[nh * 2][0] = r[0]; b_hi[nh * 2][1] = r[1];
                    b_hi[nh * 2 + 1][0] = r[2]; b_hi[nh * 2 + 1][1] = r[3];
                    ldsm4(r, stg + OFF_BL + off);
                    b_lo[nh * 2][0] = r[0]; b_lo[nh * 2][1] = r[1];
                    b_lo[nh * 2 + 1][0] = r[2]; b_lo[nh * 2 + 1][1] = r[3];
                }
            }
            // 3-pass MMA: Ah*Bh + Ah*Bl + Al*Bh
            #pragma unroll
            for (int mt = 0; mt < 4; mt++)
                #pragma unroll
                for (int nt = 0; nt < 4; nt++) {
                    mma16816(acc[mt][nt], a_hi[mt], b_hi[nt]);
                    mma16816(acc[mt][nt], a_hi[mt], b_lo[nt]);
                    mma16816(acc[mt][nt], a_lo[mt], b_hi[nt]);
                }
        }
        __syncthreads();
    }

    // ---- epilogue: direct register -> global ----
    #pragma unroll
    for (int mt = 0; mt < 4; mt++) {
        int r0 = mbase + mw * 64 + mt * 16 + (lane >> 2);
        #pragma unroll
        for (int nt = 0; nt < 4; nt++) {
            int col = nbase + nw * 32 + nt * 8 + (lane & 3) * 2;
            float b0 = 0.f, b1 = 0.f;
            if (BIAS) { b0 = bias[col]; b1 = bias[col + 1]; }
            *(float2*)(C + (size_t)r0 * ldc + col) =
                make_float2(acc[mt][nt][0] + b0, acc[mt][nt][1] + b1);
            *(float2*)(C + (size_t)(r0 + 8) * ldc + col) =
                make_float2(acc[mt][nt][2] + b0, acc[mt][nt][3] + b1);
        }
    }
}

// ---------------- row-local attention (writes split bf16 x) ----------------
__global__ __launch_bounds__(128)
void attn_kernel(const float* __restrict__ qkv,
                 unsigned short* __restrict__ xhi, unsigned short* __restrict__ xlo)
{
    __shared__ float s[16 * 768];
    const int row0 = blockIdx.x * 16;
    const int tid  = threadIdx.x;

    const float4* src = (const float4*)(qkv + (size_t)row0 * 768);
    float4* dst = (float4*)s;
    #pragma unroll
    for (int i = 0; i < 24; i++)
        dst[tid + 128 * i] = src[tid + 128 * i];
    __syncthreads();

    const int r = tid >> 3;
    const int h = tid & 7;
    const float* q  = s + r * 768 + h * 32;
    const float* k  = s + r * 768 + 256;
    const float* vv = s + r * 768 + 512;

    const float scale = 0.17677669529663687f;  // 1/sqrt(32)

    float p[8];
    #pragma unroll
    for (int g = 0; g < 8; g++) {
        float a = 0.0f;
        #pragma unroll
        for (int d = 0; d < 32; d++)
            a = fmaf(q[d], k[g * 32 + d], a);
        p[g] = a * scale;
    }
    float mx = p[0];
    #pragma unroll
    for (int g = 1; g < 8; g++) mx = fmaxf(mx, p[g]);
    float sum = 0.0f;
    #pragma unroll
    for (int g = 0; g < 8; g++) { p[g] = __expf(p[g] - mx); sum += p[g]; }
    const float inv = 1.0f / sum;
    #pragma unroll
    for (int g = 0; g < 8; g++) p[g] *= inv;

    float o[32];
    #pragma unroll
    for (int d = 0; d < 32; d++) {
        float a = 0.0f;
        #pragma unroll
        for (int g = 0; g < 8; g++)
            a = fmaf(p[g], vv[g * 32 + d], a);
        o[d] = a;
    }

    unsigned short hbuf[32], lbuf[32];
    #pragma unroll
    for (int d = 0; d < 32; d++) {
        __nv_bfloat16 hb = __float2bfloat16(o[d]);
        __nv_bfloat16 lb = __float2bfloat16(o[d] - __bfloat162float(hb));
        hbuf[d] = *(unsigned short*)&hb;
        lbuf[d] = *(unsigned short*)&lb;
    }
    size_t base = (size_t)(row0 + r) * 256 + h * 32;
    #pragma unroll
    for (int d = 0; d < 32; d += 8) {
        *(uint4*)(xhi + base + d) = *(uint4*)(hbuf + d);
        *(uint4*)(xlo + base + d) = *(uint4*)(lbuf + d);
    }
}

// ---------------- launch ----------------------------------------------------
extern "C" void kernel_launch(void* const* d_in, const int* in_sizes, int n_in,
                              void* d_out, int out_size)
{
    const float* v  = (const float*)d_in[0];
    const float* Wq = (const float*)d_in[1];
    const float* Wk = (const float*)d_in[2];
    const float* Wv = (const float*)d_in[3];
    const float* Wp = (const float*)d_in[4];
    const float* bp = (const float*)d_in[5];
    float* out = (float*)d_out;

    unsigned short *vhi, *vlo, *xhi, *xlo, *wt;
    float *qkv;
    cudaGetSymbolAddress((void**)&vhi, g_vhi);
    cudaGetSymbolAddress((void**)&vlo, g_vlo);
    cudaGetSymbolAddress((void**)&xhi, g_xhi);
    cudaGetSymbolAddress((void**)&xlo, g_xlo);
    cudaGetSymbolAddress((void**)&wt,  g_wt);
    cudaGetSymbolAddress((void**)&qkv, g_qkv);

    cudaFuncSetAttribute(gemm3_kernel<false>, cudaFuncAttributeMaxDynamicSharedMemorySize, GEMM_SMEM);
    cudaFuncSetAttribute(gemm3_kernel<true>,  cudaFuncAttributeMaxDynamicSharedMemorySize, GEMM_SMEM);

    int n4 = M_TOTAL * DIM / 4;
    split_kernel<<<(n4 + 255) / 256, 256>>>((const float4*)v, (uint2*)vhi, (uint2*)vlo, n4);
    wconv_kernel<<<dim3(256, 4), 256>>>(Wq, Wk, Wv, Wp, wt);

    dim3 grid(2, M_TOTAL / 128);  // (2, 512)
    gemm3_kernel<false><<<grid, 256, GEMM_SMEM>>>(vhi, vlo, wt + 0 * 65536, wt + 1 * 65536,
                                                  nullptr, qkv + 0,   3 * DIM);
    gemm3_kernel<false><<<grid, 256, GEMM_SMEM>>>(vhi, vlo, wt + 2 * 65536, wt + 3 * 65536,
                                                  nullptr, qkv + 256, 3 * DIM);
    gemm3_kernel<false><<<grid, 256, GEMM_SMEM>>>(vhi, vlo, wt + 4 * 65536, wt + 5 * 65536,
                                                  nullptr, qkv + 512, 3 * DIM);
    attn_kernel<<<M_TOTAL / 16, 128>>>(qkv, xhi, xlo);
    gemm3_kernel<true><<<grid, 256, GEMM_SMEM>>>(xhi, xlo, wt + 6 * 65536, wt + 7 * 65536,
                                                 bp, out, DIM);
}